// round 14
// baseline (speedup 1.0000x reference)
#include <cuda_runtime.h>
#include <cuda_fp16.h>
#include <cstdint>

// ---------------- constants ----------------
#define B_   16
#define L_   24
#define LH_  12
#define T_   400
#define D_   1024
#define E_   512
#define M_   6400
#define RIN_ 12288
#define TEMP_ 1.75f
#define ALPHA_ 0.325f
#define UNIF_ (0.675f / 24.0f)

#define OUT_LOGITS 0
#define OUT_RW     32
#define OUT_FN     416
#define OUT_POOLED 8608

// ---------------- scratch (device globals; no allocation) ----------------
__device__ __half g_Ah [(size_t)L_ * M_ * D_];   // h fp16  [l][m][k]
__device__ __half g_B1 [(size_t)L_ * E_ * D_];   // We1^T fp16 [l][n][k]
__device__ __half g_x1 [(size_t)L_ * M_ * E_];   // relu(h@We1+be1) fp16
__device__ float g_v [(size_t)L_ * E_];          // We2 . wa  per l
__device__ float g_xbar[(size_t)B_ * L_ * E_];   // softmax-weighted x1
__device__ float g_rpart[16 * 16 * 152];         // router partials

// ---------------- PTX helpers ----------------
__device__ __forceinline__ uint32_t smem_u32(const void* p) {
    uint32_t a;
    asm("{ .reg .u64 t; cvta.to.shared.u64 t, %1; cvt.u32.u64 %0, t; }" : "=r"(a) : "l"(p));
    return a;
}
__device__ __forceinline__ void cp16(uint32_t dst, const void* src) {
    asm volatile("cp.async.cg.shared.global [%0], [%1], 16;" :: "r"(dst), "l"(src));
}
__device__ __forceinline__ void cp_commit() {
    asm volatile("cp.async.commit_group;" ::: "memory");
}
template<int N>
__device__ __forceinline__ void cp_wait() {
    asm volatile("cp.async.wait_group %0;" :: "n"(N) : "memory");
}
__device__ __forceinline__ void ldsm4(uint32_t r[4], uint32_t addr) {
    asm volatile("ldmatrix.sync.aligned.m8n8.x4.shared.b16 {%0,%1,%2,%3}, [%4];"
                 : "=r"(r[0]), "=r"(r[1]), "=r"(r[2]), "=r"(r[3]) : "r"(addr));
}
__device__ __forceinline__ void mma_fp16(float d[4], const uint32_t a[4],
                                         uint32_t b0, uint32_t b1) {
    asm volatile(
        "mma.sync.aligned.m16n8k16.row.col.f32.f16.f16.f32 "
        "{%0,%1,%2,%3}, {%4,%5,%6,%7}, {%8,%9}, {%0,%1,%2,%3};"
        : "+f"(d[0]), "+f"(d[1]), "+f"(d[2]), "+f"(d[3])
        : "r"(a[0]), "r"(a[1]), "r"(a[2]), "r"(a[3]), "r"(b0), "r"(b1));
}

union H8 { __half b[8]; uint4 u; };

// ---------------- conversion: h -> row-major fp16 ----------------
__global__ void __launch_bounds__(256)
conv_h_kernel(const float* __restrict__ h, __half* __restrict__ Ah, int l_base)
{
    const int l  = l_base + blockIdx.z;
    const int gi = blockIdx.x * 256 + threadIdx.x;
    const int m  = gi >> 7;
    const int k0 = (gi & 127) * 8;
    const int b  = m / 400, t = m - b * 400;

    const float* src = h + (((size_t)(b * L_ + l) * T_ + t) * (size_t)D_ + k0);
    float4 v0 = *(const float4*)src;
    float4 v1 = *(const float4*)(src + 4);
    float v[8] = {v0.x, v0.y, v0.z, v0.w, v1.x, v1.y, v1.z, v1.w};

    H8 hv;
#pragma unroll
    for (int i = 0; i < 8; i++) hv.b[i] = __float2half(v[i]);
    *(uint4*)(Ah + ((size_t)l * M_ + m) * (size_t)D_ + k0) = hv.u;
}

// ---------------- conv_w: We1[l][K][512] -> [l][n][K] fp16 (transposed) ----------
__global__ void __launch_bounds__(256)
conv_w_kernel(const float* __restrict__ W, __half* __restrict__ Bo, int l_base)
{
    const int K = D_;
    const int l  = l_base + blockIdx.z;
    const int n0 = blockIdx.y * 64;
    const int k0 = blockIdx.x * 64;
    const int tid = threadIdx.x;

    __shared__ float s_w[64 * 65];

#pragma unroll
    for (int it = 0; it < 4; it++) {
        const int idx = it * 256 + tid;
        const int kr = idx >> 4;
        const int c4 = idx & 15;
        float4 v = *(const float4*)(W + ((size_t)l * K + k0 + kr) * 512 + n0 + c4 * 4);
        float* d = s_w + kr * 65 + c4 * 4;
        d[0] = v.x; d[1] = v.y; d[2] = v.z; d[3] = v.w;
    }
    __syncthreads();

#pragma unroll
    for (int it = 0; it < 2; it++) {
        const int idx = it * 256 + tid;
        const int nl  = idx >> 3;
        const int kc8 = idx & 7;
        H8 hv;
#pragma unroll
        for (int j = 0; j < 8; j++)
            hv.b[j] = __float2half(s_w[(kc8 * 8 + j) * 65 + nl]);
        const size_t o = ((size_t)l * 512 + n0 + nl) * (size_t)K + k0 + kc8 * 8;
        *(uint4*)(Bo + o) = hv.u;
    }
}

// ---------------- v = We2 . wa ----------------
__global__ void __launch_bounds__(256)
vwa_kernel(const float* __restrict__ We2, const float* __restrict__ wa,
           float* __restrict__ v)
{
    const int l = blockIdx.y;
    const int e0 = blockIdx.x * 128;
    const int tid = threadIdx.x;
    const int lane = tid & 31, wid = tid >> 5;
    __shared__ float s_wa[E_];
    for (int f = tid; f < E_; f += 256) s_wa[f] = wa[f];
    __syncthreads();
    for (int e = e0 + wid; e < e0 + 128; e += 8) {
        const float* row = We2 + ((size_t)l * E_ + e) * E_;
        float s = 0.f;
        for (int f = lane; f < E_; f += 32) s += row[f] * s_wa[f];
#pragma unroll
        for (int o = 16; o; o >>= 1) s += __shfl_xor_sync(0xffffffffu, s, o);
        if (lane == 0) v[l * E_ + e] = s;
    }
}

// ---------------- fp16 single-term GEMM, fragment double-buffered ----------------
// x1 = relu(h @ We1 + be1) -> fp16; BK=64, stages 32KB x3, 2 CTAs/SM.
#define STAGE_ 32768
#define SMEM_TOT (3 * STAGE_)

__global__ void __launch_bounds__(256, 2)
mma_gemm_kernel(const __half* __restrict__ Ag, const __half* __restrict__ Bw,
                const float* __restrict__ bias, __half* __restrict__ Cx, int l_base)
{
    constexpr int K = D_;
    constexpr int NK = K / 64;          // 16 iters
    extern __shared__ __align__(128) char smem[];
    const uint32_t sb = smem_u32(smem);
    const int tid = threadIdx.x;
    const int lane = tid & 31, wid = tid >> 5;
    const int nt = blockIdx.x, bm = blockIdx.y;
    const int l = l_base + blockIdx.z;

    const char* srcs[8];
    uint32_t dsto[8];
#pragma unroll
    for (int t = 0; t < 8; t++) {
        const int j = tid + t * 256;
        const bool isA = j < 1024;
        const int idx = j & 1023;
        const int row = idx >> 3;
        const int c   = idx & 7;
        size_t base;
        const __half* gb;
        if (isA) {
            gb = Ag;
            base = ((size_t)l * M_ + (size_t)bm * 128 + row) * (size_t)K + c * 8;
        } else {
            gb = Bw;
            base = ((size_t)l * 512 + (size_t)nt * 128 + row) * (size_t)K + c * 8;
        }
        srcs[t] = (const char*)(gb + base);
        dsto[t] = (isA ? 0u : 16384u) + (uint32_t)row * 128u +
                  (uint32_t)((c ^ (row & 7)) * 16);
    }

#define ISSUE_STAGE(S)                                              \
    do {                                                            \
        const uint32_t stb_ = sb + (uint32_t)(S) * STAGE_;          \
        _Pragma("unroll")                                           \
        for (int t = 0; t < 8; t++) cp16(stb_ + dsto[t], srcs[t]);  \
        _Pragma("unroll")                                           \
        for (int t = 0; t < 8; t++) srcs[t] += 128;                 \
        cp_commit();                                                \
    } while (0)

    ISSUE_STAGE(0);
    ISSUE_STAGE(1);

    float acc[4][4][4];
#pragma unroll
    for (int i = 0; i < 4; i++)
#pragma unroll
        for (int j = 0; j < 4; j++)
#pragma unroll
            for (int r = 0; r < 4; r++) acc[i][j][r] = 0.f;

    const int wm = (wid & 1) * 64;
    const int wn = (wid >> 1) * 32;
    const int lr = lane & 15;
    const int lc = lane >> 4;

#define LOADFRAG(AF, BF, KS)                                               \
    do {                                                                   \
        const int ch_ = (KS) * 2 + lc;                                     \
        _Pragma("unroll")                                                  \
        for (int i = 0; i < 4; i++) {                                      \
            const int row_ = wm + i * 16 + lr;                             \
            ldsm4(AF[i], sA + (uint32_t)row_ * 128u +                      \
                          (uint32_t)(((ch_) ^ (row_ & 7)) * 16));          \
        }                                                                  \
        _Pragma("unroll")                                                  \
        for (int j = 0; j < 2; j++) {                                      \
            const int row_ = wn + j * 16 + lr;                             \
            ldsm4(BF[j], sB + (uint32_t)row_ * 128u +                      \
                          (uint32_t)(((ch_) ^ (row_ & 7)) * 16));          \
        }                                                                  \
    } while (0)

#define MMASET(AF, BF)                                                     \
    do {                                                                   \
        _Pragma("unroll")                                                  \
        for (int i = 0; i < 4; i++)                                        \
            _Pragma("unroll")                                              \
            for (int j = 0; j < 2; j++)                                    \
                _Pragma("unroll")                                          \
                for (int hf = 0; hf < 2; hf++)                             \
                    mma_fp16(acc[i][j * 2 + hf], AF[i], BF[j][hf], BF[j][hf + 2]); \
    } while (0)

    for (int kc = 0; kc < NK; kc++) {
        cp_wait<1>();
        __syncthreads();
        const int s = kc % 3;
        if (kc + 2 < NK) { ISSUE_STAGE((kc + 2) % 3); }
        else             { cp_commit(); }

        const uint32_t sA = sb + (uint32_t)s * STAGE_;
        const uint32_t sB = sA + 16384u;

        uint32_t a0[4][4], b0[2][4], a1[4][4], b1[2][4];
        LOADFRAG(a0, b0, 0);
        LOADFRAG(a1, b1, 1);
        MMASET(a0, b0);
        LOADFRAG(a0, b0, 2);
        MMASET(a1, b1);
        LOADFRAG(a1, b1, 3);
        MMASET(a0, b0);
        MMASET(a1, b1);
    }
#undef ISSUE_STAGE
#undef LOADFRAG
#undef MMASET

    // epilogue: bias + relu -> fp16 store (half2)
    const int lq = lane >> 2;
    const int lp = (lane & 3) * 2;
#pragma unroll
    for (int j2 = 0; j2 < 4; j2++) {
        const int n_g = nt * 128 + wn + j2 * 8 + lp;
        const float b0v = bias[l * 512 + n_g];
        const float b1v = bias[l * 512 + n_g + 1];
#pragma unroll
        for (int i = 0; i < 4; i++) {
#pragma unroll
            for (int rh = 0; rh < 2; rh++) {
                const int m_g = bm * 128 + wm + i * 16 + lq + rh * 8;
                float v0 = fmaxf(acc[i][j2][rh * 2 + 0] + b0v, 0.f);
                float v1 = fmaxf(acc[i][j2][rh * 2 + 1] + b1v, 0.f);
                __half2 hv;
                hv.x = __float2half(v0);
                hv.y = __float2half(v1);
                *(__half2*)(Cx + ((size_t)l * M_ + m_g) * 512 + n_g) = hv;
            }
        }
    }
}

// ---------------- pool2: single-pass online softmax over fp16 x1 ----------------
#define TC_ 16
#define P2_XBUF (2 * TC_ * E_ * 2)                 // 32 KB (fp16 tiles)
#define P2_SMEM (P2_XBUF + E_ * 4 + 256)

__global__ void __launch_bounds__(256)
pool2_kernel(const __half* __restrict__ x1, const float* __restrict__ v,
             float* __restrict__ xbar, int l_base)
{
    extern __shared__ __align__(16) char psm[];
    __half* s_x = (__half*)psm;                    // [2][TC_][E_] fp16
    float* s_v  = (float*)(psm + P2_XBUF);
    float* s_p  = (float*)(psm + P2_XBUF + E_ * 4);
    float* s_c  = s_p + TC_;
    const uint32_t sxb = smem_u32(s_x);

    const int b = blockIdx.x / LH_;
    const int l = l_base + blockIdx.x % LH_;
    const char* xbase = (const char*)(x1 + ((size_t)l * M_ + (size_t)b * T_) * E_);

    const int tid = threadIdx.x;
    const int lane = tid & 31, wid = tid >> 5;

    for (int e = tid; e < E_; e += 256) s_v[e] = v[l * E_ + e];
    if (tid == 0) { s_c[1] = 0.f; s_c[2] = -1e30f; }

    // tile = 16 rows x 512 halves = 16 KB = 1024 chunks; 4 per thread
#pragma unroll
    for (int i = 0; i < 4; i++) {
        const int j = i * 256 + tid;
        cp16(sxb + (uint32_t)j * 16u, xbase + (size_t)j * 16);
    }
    cp_commit();

    float acc0 = 0.f, acc1 = 0.f;
    const int e0 = tid, e1 = tid + 256;

    for (int tile = 0; tile < T_ / TC_; tile++) {
        const int buf = tile & 1;
        if (tile + 1 < T_ / TC_) {
            const uint32_t db = sxb + (uint32_t)((tile + 1) & 1) * (TC_ * E_ * 2);
            const char* src = xbase + (size_t)(tile + 1) * TC_ * E_ * 2;
#pragma unroll
            for (int i = 0; i < 4; i++) {
                const int j = i * 256 + tid;
                cp16(db + (uint32_t)j * 16u, src + (size_t)j * 16);
            }
            cp_commit();
            cp_wait<1>();
        } else {
            cp_wait<0>();
        }
        __syncthreads();

        const __half* xt = s_x + buf * (TC_ * E_);
#pragma unroll
        for (int rr = 0; rr < 2; rr++) {
            const int r = wid + rr * 8;
            const __half* row = xt + r * E_;
            float s = 0.f;
#pragma unroll 4
            for (int e = lane; e < E_; e += 32) s += __half2float(row[e]) * s_v[e];
#pragma unroll
            for (int o = 16; o; o >>= 1) s += __shfl_xor_sync(0xffffffffu, s, o);
            if (lane == 0) s_p[r] = s;
        }
        __syncthreads();

        if (wid == 0) {
            float sc = (lane < TC_) ? s_p[lane] : -1e30f;
            float tm = sc;
#pragma unroll
            for (int o = 16; o; o >>= 1) tm = fmaxf(tm, __shfl_xor_sync(0xffffffffu, tm, o));
            const float m_old = s_c[2];
            const float m_new = fmaxf(m_old, tm);
            const float fac = expf(m_old - m_new);
            float p = (lane < TC_) ? expf(sc - m_new) : 0.f;
            float ps = p;
#pragma unroll
            for (int o = 16; o; o >>= 1) ps += __shfl_xor_sync(0xffffffffu, ps, o);
            if (lane < TC_) s_p[lane] = p;
            if (lane == 0) {
                s_c[0] = fac;
                s_c[1] = s_c[1] * fac + ps;
                s_c[2] = m_new;
            }
        }
        __syncthreads();

        const float fac = s_c[0];
        acc0 *= fac;
        acc1 *= fac;
#pragma unroll
        for (int r = 0; r < TC_; r++) {
            const float p = s_p[r];
            acc0 += p * __half2float(xt[r * E_ + e0]);
            acc1 += p * __half2float(xt[r * E_ + e1]);
        }
        __syncthreads();
    }

    const float inv = 1.0f / s_c[1];
    float* dst = xbar + ((size_t)b * L_ + l) * E_;
    dst[e0] = acc0 * inv;
    dst[e1] = acc1 * inv;
}

// ---------------- pooled = xbar @ We2 + be2 ----------------
__global__ void __launch_bounds__(128)
pooledg_kernel(const float* __restrict__ xbar, const float* __restrict__ We2,
               const float* __restrict__ be2, float* __restrict__ pooled, int l_base)
{
    const int l = l_base + blockIdx.y;
    const int f = blockIdx.x * 128 + threadIdx.x;
    const int tid = threadIdx.x;

    __shared__ float s_x[B_ * E_];
    for (int i = tid; i < B_ * E_; i += 128) {
        const int b = i >> 9, e = i & 511;
        s_x[i] = xbar[((size_t)b * L_ + l) * E_ + e];
    }
    __syncthreads();

    float acc[B_];
#pragma unroll
    for (int b = 0; b < B_; b++) acc[b] = 0.f;

    const float* wcol = We2 + (size_t)l * E_ * E_ + f;
#pragma unroll 4
    for (int e = 0; e < E_; e++) {
        const float w = wcol[(size_t)e * E_];
#pragma unroll
        for (int b = 0; b < B_; b++) acc[b] += s_x[b * E_ + e] * w;
    }
    const float bias = be2[l * E_ + f];
#pragma unroll
    for (int b = 0; b < B_; b++)
        pooled[((size_t)b * L_ + l) * E_ + f] = acc[b] + bias;
}

// ---------------- router GEMM: partial sums over 16 k-slices ----------------
__global__ void __launch_bounds__(256)
router_gemm_kernel(const float* __restrict__ pooled,
                   const float* __restrict__ Wr1, const float* __restrict__ Wn,
                   float* __restrict__ part)
{
    const int s = blockIdx.x, b = blockIdx.y;
    const int tid = threadIdx.x;
    const float* ri = pooled + (size_t)b * RIN_ + s * 768;

    float acc = 0.f;
    if (tid < 128) {
        const float* w = Wr1 + (size_t)s * 768 * 128 + tid;
#pragma unroll 8
        for (int k = 0; k < 768; k++) acc += ri[k] * w[(size_t)k * 128];
        part[(s * 16 + b) * 152 + tid] = acc;
    } else if (tid < 152) {
        const float* w = Wn + (size_t)s * 768 * 24 + (tid - 128);
#pragma unroll 8
        for (int k = 0; k < 768; k++) acc += ri[k] * w[(size_t)k * 24];
        part[(s * 16 + b) * 152 + tid] = acc;
    }
}

// ---------------- router tail ----------------
__global__ void __launch_bounds__(256)
router_tail_kernel(const float* __restrict__ pooled, const float* __restrict__ noise,
                   const float* __restrict__ part,
                   const float* __restrict__ br1,
                   const float* __restrict__ Wr2, const float* __restrict__ br2,
                   const float* __restrict__ bn,
                   const float* __restrict__ ln_g, const float* __restrict__ ln_b,
                   const float* __restrict__ Wc1, const float* __restrict__ bc1,
                   const float* __restrict__ Wc2, const float* __restrict__ bc2,
                   float* __restrict__ out_logits, float* __restrict__ out_rw,
                   float* __restrict__ out_fn)
{
    const int b = blockIdx.x;
    const int tid = threadIdx.x;
    const int lane = tid & 31, wid = tid >> 5;
    const float* ri = pooled + (size_t)b * RIN_;

    __shared__ float s_rh[128];
    __shared__ float s_nlin[L_];
    __shared__ float s_rw[L_];
    __shared__ float s_f[E_];
    __shared__ float s_hc[256];
    __shared__ float s_red[32];

    if (tid < 152) {
        float acc = 0.f;
#pragma unroll
        for (int s = 0; s < 16; s++) acc += part[(s * 16 + b) * 152 + tid];
        if (tid < 128) s_rh[tid] = fmaxf(acc + br1[tid], 0.f);
        else           s_nlin[tid - 128] = acc + bn[tid - 128];
    }
    __syncthreads();

    if (tid < L_) {
        float acc = 0.f;
#pragma unroll
        for (int k = 0; k < 128; k++) acc += s_rh[k] * Wr2[k * L_ + tid];
        const float lg = acc + br2[tid];
        const float x = s_nlin[tid];
        const float ns = (x > 20.f) ? x : log1pf(expf(x));
        const float z = (lg + noise[b * L_ + tid] * ns) / TEMP_;
        const float sig = 1.f / (1.f + expf(-z));
        const float rw = ALPHA_ * sig + UNIF_;
        s_rw[tid] = rw;
        out_rw[b * L_ + tid] = rw;
    }
    __syncthreads();

    float fv[2];
#pragma unroll
    for (int rr = 0; rr < 2; rr++) {
        const int e = tid + rr * 256;
        float acc = 0.f;
#pragma unroll
        for (int ll = 0; ll < L_; ll++) acc += ri[ll * E_ + e] * s_rw[ll];
        s_f[e] = acc;
        fv[rr] = acc;
    }
    float lsum = fv[0] + fv[1];
    float lsq  = fv[0] * fv[0] + fv[1] * fv[1];
#pragma unroll
    for (int o = 16; o; o >>= 1) {
        lsum += __shfl_xor_sync(0xffffffffu, lsum, o);
        lsq  += __shfl_xor_sync(0xffffffffu, lsq,  o);
    }
    if (lane == 0) { s_red[wid] = lsum; s_red[wid + 8] = lsq; }
    __syncthreads();
    if (tid == 0) {
        float su = 0.f, sq = 0.f;
        for (int w = 0; w < 8; w++) { su += s_red[w]; sq += s_red[w + 8]; }
        const float mu = su / (float)E_;
        const float var = sq / (float)E_ - mu * mu;
        s_red[0] = mu;
        s_red[1] = rsqrtf(var + 1e-5f);
    }
    __syncthreads();
    const float mu = s_red[0], rstd = s_red[1];
#pragma unroll
    for (int rr = 0; rr < 2; rr++) {
        const int e = tid + rr * 256;
        const float fn = (s_f[e] - mu) * rstd * ln_g[e] + ln_b[e];
        s_f[e] = fn;
        out_fn[(size_t)b * E_ + e] = fn;
    }
    __syncthreads();

    {
        const float* w = Wc1 + tid;
        float acc = 0.f;
#pragma unroll 8
        for (int e = 0; e < E_; e++) { acc += s_f[e] * (*w); w += 256; }
        s_hc[tid] = fmaxf(acc + bc1[tid], 0.f);
    }
    __syncthreads();

    if (tid < 2) {
        float acc = 0.f;
#pragma unroll 8
        for (int j = 0; j < 256; j++) acc += s_hc[j] * Wc2[j * 2 + tid];
        out_logits[b * 2 + tid] = acc + bc2[tid];
    }
}

// ---------------- launch: two-stream fork/join pipeline ----------
extern "C" void kernel_launch(void* const* d_in, const int* in_sizes, int n_in,
                              void* d_out, int out_size)
{
    const float* h    = (const float*)d_in[0];
    const float* noise= (const float*)d_in[1];
    const float* We1  = (const float*)d_in[2];
    const float* be1  = (const float*)d_in[3];
    const float* We2  = (const float*)d_in[4];
    const float* be2  = (const float*)d_in[5];
    const float* wa   = (const float*)d_in[6];
    const float* Wr1  = (const float*)d_in[8];
    const float* br1  = (const float*)d_in[9];
    const float* Wr2  = (const float*)d_in[10];
    const float* br2  = (const float*)d_in[11];
    const float* Wn   = (const float*)d_in[12];
    const float* bn   = (const float*)d_in[13];
    const float* ln_g = (const float*)d_in[14];
    const float* ln_b = (const float*)d_in[15];
    const float* Wc1  = (const float*)d_in[16];
    const float* bc1  = (const float*)d_in[17];
    const float* Wc2  = (const float*)d_in[18];
    const float* bc2  = (const float*)d_in[19];

    __half *Ah, *B1, *x1;
    float *v, *xbar, *rpart;
    cudaGetSymbolAddress((void**)&Ah,  g_Ah);
    cudaGetSymbolAddress((void**)&B1,  g_B1);
    cudaGetSymbolAddress((void**)&x1,  g_x1);
    cudaGetSymbolAddress((void**)&v,   g_v);
    cudaGetSymbolAddress((void**)&xbar, g_xbar);
    cudaGetSymbolAddress((void**)&rpart, g_rpart);

    float* out = (float*)d_out;
    float* out_logits = out + OUT_LOGITS;
    float* out_rw     = out + OUT_RW;
    float* out_fn     = out + OUT_FN;
    float* out_pooled = out + OUT_POOLED;

    cudaFuncSetAttribute(mma_gemm_kernel,
                         cudaFuncAttributeMaxDynamicSharedMemorySize, SMEM_TOT);
    cudaFuncSetAttribute(pool2_kernel,
                         cudaFuncAttributeMaxDynamicSharedMemorySize, P2_SMEM);

    cudaStream_t sp;
    cudaStreamCreateWithFlags(&sp, cudaStreamNonBlocking);
    cudaEvent_t e1, e2, e3, e5;
    cudaEventCreateWithFlags(&e1, cudaEventDisableTiming);
    cudaEventCreateWithFlags(&e2, cudaEventDisableTiming);
    cudaEventCreateWithFlags(&e3, cudaEventDisableTiming);
    cudaEventCreateWithFlags(&e5, cudaEventDisableTiming);

    // main: conv half1
    conv_h_kernel<<<dim3(3200, 1, LH_), 256>>>(h, Ah, 0);
    conv_w_kernel<<<dim3(16, 8, LH_), 256>>>(We1, B1, 0);
    cudaEventRecord(e1, 0);

    // side: conv half2 + vwa
    cudaStreamWaitEvent(sp, e1, 0);
    conv_h_kernel<<<dim3(3200, 1, LH_), 256, 0, sp>>>(h, Ah, LH_);
    conv_w_kernel<<<dim3(16, 8, LH_), 256, 0, sp>>>(We1, B1, LH_);
    vwa_kernel<<<dim3(4, L_), 256, 0, sp>>>(We2, wa, v);
    cudaEventRecord(e2, sp);

    // main: gemm half1
    mma_gemm_kernel<<<dim3(4, 50, LH_), 256, SMEM_TOT>>>(Ah, B1, be1, x1, 0);
    cudaEventRecord(e3, 0);

    // main: gemm half2
    cudaStreamWaitEvent(0, e2, 0);
    mma_gemm_kernel<<<dim3(4, 50, LH_), 256, SMEM_TOT>>>(Ah, B1, be1, x1, LH_);

    // side: pool half1
    cudaStreamWaitEvent(sp, e3, 0);
    pool2_kernel<<<B_ * LH_, 256, P2_SMEM, sp>>>(x1, v, xbar, 0);
    pooledg_kernel<<<dim3(4, LH_), 128, 0, sp>>>(xbar, We2, be2, out_pooled, 0);
    cudaEventRecord(e5, sp);

    // main: pool half2, join, router
    pool2_kernel<<<B_ * LH_, 256, P2_SMEM>>>(x1, v, xbar, LH_);
    pooledg_kernel<<<dim3(4, LH_), 128>>>(xbar, We2, be2, out_pooled, LH_);
    cudaStreamWaitEvent(0, e5, 0);
    router_gemm_kernel<<<dim3(16, 16), 256>>>(out_pooled, Wr1, Wn, rpart);
    router_tail_kernel<<<B_, 256>>>(out_pooled, noise, rpart, br1, Wr2, br2, bn,
                                    ln_g, ln_b, Wc1, bc1, Wc2, bc2,
                                    out_logits, out_rw, out_fn);
}

// round 15
// speedup vs baseline: 1.0254x; 1.0254x over previous
#include <cuda_runtime.h>
#include <cuda_fp16.h>
#include <cstdint>

// ---------------- constants ----------------
#define B_   16
#define L_   24
#define LH_  12
#define LQ_  6
#define T_   400
#define D_   1024
#define E_   512
#define M_   6400
#define RIN_ 12288
#define TEMP_ 1.75f
#define ALPHA_ 0.325f
#define UNIF_ (0.675f / 24.0f)

#define OUT_LOGITS 0
#define OUT_RW     32
#define OUT_FN     416
#define OUT_POOLED 8608

// ---------------- scratch (device globals; no allocation) ----------------
__device__ __half g_Ah [(size_t)L_ * M_ * D_];   // h fp16  [l][m][k]
__device__ __half g_B1 [(size_t)L_ * E_ * D_];   // We1^T fp16 [l][n][k]
__device__ float g_x1[(size_t)L_ * M_ * E_];     // relu(h@We1+be1) fp32
__device__ float g_v [(size_t)L_ * E_];          // We2 . wa  per l
__device__ float g_xbar[(size_t)B_ * L_ * E_];   // softmax-weighted x1
__device__ float g_rpart[16 * 16 * 152];         // router partials

// ---------------- PTX helpers ----------------
__device__ __forceinline__ uint32_t smem_u32(const void* p) {
    uint32_t a;
    asm("{ .reg .u64 t; cvta.to.shared.u64 t, %1; cvt.u32.u64 %0, t; }" : "=r"(a) : "l"(p));
    return a;
}
__device__ __forceinline__ void cp16(uint32_t dst, const void* src) {
    asm volatile("cp.async.cg.shared.global [%0], [%1], 16;" :: "r"(dst), "l"(src));
}
__device__ __forceinline__ void cp_commit() {
    asm volatile("cp.async.commit_group;" ::: "memory");
}
template<int N>
__device__ __forceinline__ void cp_wait() {
    asm volatile("cp.async.wait_group %0;" :: "n"(N) : "memory");
}
__device__ __forceinline__ void ldsm4(uint32_t r[4], uint32_t addr) {
    asm volatile("ldmatrix.sync.aligned.m8n8.x4.shared.b16 {%0,%1,%2,%3}, [%4];"
                 : "=r"(r[0]), "=r"(r[1]), "=r"(r[2]), "=r"(r[3]) : "r"(addr));
}
__device__ __forceinline__ void mma_fp16(float d[4], const uint32_t a[4],
                                         uint32_t b0, uint32_t b1) {
    asm volatile(
        "mma.sync.aligned.m16n8k16.row.col.f32.f16.f16.f32 "
        "{%0,%1,%2,%3}, {%4,%5,%6,%7}, {%8,%9}, {%0,%1,%2,%3};"
        : "+f"(d[0]), "+f"(d[1]), "+f"(d[2]), "+f"(d[3])
        : "r"(a[0]), "r"(a[1]), "r"(a[2]), "r"(a[3]), "r"(b0), "r"(b1));
}

union H8 { __half b[8]; uint4 u; };

// ---------------- conversion: h -> row-major fp16 ----------------
__global__ void __launch_bounds__(256)
conv_h_kernel(const float* __restrict__ h, __half* __restrict__ Ah, int l_base)
{
    const int l  = l_base + blockIdx.z;
    const int gi = blockIdx.x * 256 + threadIdx.x;
    const int m  = gi >> 7;
    const int k0 = (gi & 127) * 8;
    const int b  = m / 400, t = m - b * 400;

    const float* src = h + (((size_t)(b * L_ + l) * T_ + t) * (size_t)D_ + k0);
    float4 v0 = *(const float4*)src;
    float4 v1 = *(const float4*)(src + 4);
    float v[8] = {v0.x, v0.y, v0.z, v0.w, v1.x, v1.y, v1.z, v1.w};

    H8 hv;
#pragma unroll
    for (int i = 0; i < 8; i++) hv.b[i] = __float2half(v[i]);
    *(uint4*)(Ah + ((size_t)l * M_ + m) * (size_t)D_ + k0) = hv.u;
}

// ---------------- conv_w: We1[l][K][512] -> [l][n][K] fp16 (transposed) ----------
__global__ void __launch_bounds__(256)
conv_w_kernel(const float* __restrict__ W, __half* __restrict__ Bo, int l_base)
{
    const int K = D_;
    const int l  = l_base + blockIdx.z;
    const int n0 = blockIdx.y * 64;
    const int k0 = blockIdx.x * 64;
    const int tid = threadIdx.x;

    __shared__ float s_w[64 * 65];

#pragma unroll
    for (int it = 0; it < 4; it++) {
        const int idx = it * 256 + tid;
        const int kr = idx >> 4;
        const int c4 = idx & 15;
        float4 v = *(const float4*)(W + ((size_t)l * K + k0 + kr) * 512 + n0 + c4 * 4);
        float* d = s_w + kr * 65 + c4 * 4;
        d[0] = v.x; d[1] = v.y; d[2] = v.z; d[3] = v.w;
    }
    __syncthreads();

#pragma unroll
    for (int it = 0; it < 2; it++) {
        const int idx = it * 256 + tid;
        const int nl  = idx >> 3;
        const int kc8 = idx & 7;
        H8 hv;
#pragma unroll
        for (int j = 0; j < 8; j++)
            hv.b[j] = __float2half(s_w[(kc8 * 8 + j) * 65 + nl]);
        const size_t o = ((size_t)l * 512 + n0 + nl) * (size_t)K + k0 + kc8 * 8;
        *(uint4*)(Bo + o) = hv.u;
    }
}

// ---------------- v = We2 . wa ----------------
__global__ void __launch_bounds__(256)
vwa_kernel(const float* __restrict__ We2, const float* __restrict__ wa,
           float* __restrict__ v)
{
    const int l = blockIdx.y;
    const int e0 = blockIdx.x * 128;
    const int tid = threadIdx.x;
    const int lane = tid & 31, wid = tid >> 5;
    __shared__ float s_wa[E_];
    for (int f = tid; f < E_; f += 256) s_wa[f] = wa[f];
    __syncthreads();
    for (int e = e0 + wid; e < e0 + 128; e += 8) {
        const float* row = We2 + ((size_t)l * E_ + e) * E_;
        float s = 0.f;
        for (int f = lane; f < E_; f += 32) s += row[f] * s_wa[f];
#pragma unroll
        for (int o = 16; o; o >>= 1) s += __shfl_xor_sync(0xffffffffu, s, o);
        if (lane == 0) v[l * E_ + e] = s;
    }
}

// ---------------- fp16 single-term GEMM, fragment double-buffered ----------------
// x1 = relu(h @ We1 + be1) -> fp32; BK=64, stages 32KB x3, 2 CTAs/SM.
#define STAGE_ 32768
#define SMEM_TOT (3 * STAGE_)

__global__ void __launch_bounds__(256, 2)
mma_gemm_kernel(const __half* __restrict__ Ag, const __half* __restrict__ Bw,
                const float* __restrict__ bias, float* __restrict__ Cf, int l_base)
{
    constexpr int K = D_;
    constexpr int NK = K / 64;          // 16 iters
    extern __shared__ __align__(128) char smem[];
    const uint32_t sb = smem_u32(smem);
    const int tid = threadIdx.x;
    const int lane = tid & 31, wid = tid >> 5;
    const int nt = blockIdx.x, bm = blockIdx.y;
    const int l = l_base + blockIdx.z;

    const char* srcs[8];
    uint32_t dsto[8];
#pragma unroll
    for (int t = 0; t < 8; t++) {
        const int j = tid + t * 256;
        const bool isA = j < 1024;
        const int idx = j & 1023;
        const int row = idx >> 3;
        const int c   = idx & 7;
        size_t base;
        const __half* gb;
        if (isA) {
            gb = Ag;
            base = ((size_t)l * M_ + (size_t)bm * 128 + row) * (size_t)K + c * 8;
        } else {
            gb = Bw;
            base = ((size_t)l * 512 + (size_t)nt * 128 + row) * (size_t)K + c * 8;
        }
        srcs[t] = (const char*)(gb + base);
        dsto[t] = (isA ? 0u : 16384u) + (uint32_t)row * 128u +
                  (uint32_t)((c ^ (row & 7)) * 16);
    }

#define ISSUE_STAGE(S)                                              \
    do {                                                            \
        const uint32_t stb_ = sb + (uint32_t)(S) * STAGE_;          \
        _Pragma("unroll")                                           \
        for (int t = 0; t < 8; t++) cp16(stb_ + dsto[t], srcs[t]);  \
        _Pragma("unroll")                                           \
        for (int t = 0; t < 8; t++) srcs[t] += 128;                 \
        cp_commit();                                                \
    } while (0)

    ISSUE_STAGE(0);
    ISSUE_STAGE(1);

    float acc[4][4][4];
#pragma unroll
    for (int i = 0; i < 4; i++)
#pragma unroll
        for (int j = 0; j < 4; j++)
#pragma unroll
            for (int r = 0; r < 4; r++) acc[i][j][r] = 0.f;

    const int wm = (wid & 1) * 64;
    const int wn = (wid >> 1) * 32;
    const int lr = lane & 15;
    const int lc = lane >> 4;

#define LOADFRAG(AF, BF, KS)                                               \
    do {                                                                   \
        const int ch_ = (KS) * 2 + lc;                                     \
        _Pragma("unroll")                                                  \
        for (int i = 0; i < 4; i++) {                                      \
            const int row_ = wm + i * 16 + lr;                             \
            ldsm4(AF[i], sA + (uint32_t)row_ * 128u +                      \
                          (uint32_t)(((ch_) ^ (row_ & 7)) * 16));          \
        }                                                                  \
        _Pragma("unroll")                                                  \
        for (int j = 0; j < 2; j++) {                                      \
            const int row_ = wn + j * 16 + lr;                             \
            ldsm4(BF[j], sB + (uint32_t)row_ * 128u +                      \
                          (uint32_t)(((ch_) ^ (row_ & 7)) * 16));          \
        }                                                                  \
    } while (0)

#define MMASET(AF, BF)                                                     \
    do {                                                                   \
        _Pragma("unroll")                                                  \
        for (int i = 0; i < 4; i++)                                        \
            _Pragma("unroll")                                              \
            for (int j = 0; j < 2; j++)                                    \
                _Pragma("unroll")                                          \
                for (int hf = 0; hf < 2; hf++)                             \
                    mma_fp16(acc[i][j * 2 + hf], AF[i], BF[j][hf], BF[j][hf + 2]); \
    } while (0)

    for (int kc = 0; kc < NK; kc++) {
        cp_wait<1>();
        __syncthreads();
        const int s = kc % 3;
        if (kc + 2 < NK) { ISSUE_STAGE((kc + 2) % 3); }
        else             { cp_commit(); }

        const uint32_t sA = sb + (uint32_t)s * STAGE_;
        const uint32_t sB = sA + 16384u;

        uint32_t a0[4][4], b0[2][4], a1[4][4], b1[2][4];
        LOADFRAG(a0, b0, 0);
        LOADFRAG(a1, b1, 1);
        MMASET(a0, b0);
        LOADFRAG(a0, b0, 2);
        MMASET(a1, b1);
        LOADFRAG(a1, b1, 3);
        MMASET(a0, b0);
        MMASET(a1, b1);
    }
#undef ISSUE_STAGE
#undef LOADFRAG
#undef MMASET

    const int lq = lane >> 2;
    const int lp = (lane & 3) * 2;
#pragma unroll
    for (int j2 = 0; j2 < 4; j2++) {
        const int n_g = nt * 128 + wn + j2 * 8 + lp;
        const float b0v = bias[l * 512 + n_g];
        const float b1v = bias[l * 512 + n_g + 1];
#pragma unroll
        for (int i = 0; i < 4; i++) {
#pragma unroll
            for (int rh = 0; rh < 2; rh++) {
                const int m_g = bm * 128 + wm + i * 16 + lq + rh * 8;
                float v0 = fmaxf(acc[i][j2][rh * 2 + 0] + b0v, 0.f);
                float v1 = fmaxf(acc[i][j2][rh * 2 + 1] + b1v, 0.f);
                const size_t o = ((size_t)l * M_ + m_g) * 512 + n_g;
                *(float2*)(Cf + o) = make_float2(v0, v1);
            }
        }
    }
}

// ---------------- pool2: single-pass online softmax + weighted sum ----------------
#define TC_ 16
#define P2_XBUF (2 * TC_ * E_ * 4)
#define P2_SMEM (P2_XBUF + E_ * 4 + 256)

__global__ void __launch_bounds__(256)
pool2_kernel(const float* __restrict__ x1, const float* __restrict__ v,
             float* __restrict__ xbar, int l_base)
{
    extern __shared__ __align__(16) char psm[];
    float* s_x  = (float*)psm;
    float* s_v  = (float*)(psm + P2_XBUF);
    float* s_p  = (float*)(psm + P2_XBUF + E_ * 4);
    float* s_c  = s_p + TC_;
    const uint32_t sxb = smem_u32(s_x);

    const int b = blockIdx.x / LH_;
    const int l = l_base + blockIdx.x % LH_;
    const char* xbase = (const char*)(x1 + ((size_t)l * M_ + (size_t)b * T_) * E_);

    const int tid = threadIdx.x;
    const int lane = tid & 31, wid = tid >> 5;

    for (int e = tid; e < E_; e += 256) s_v[e] = v[l * E_ + e];
    if (tid == 0) { s_c[1] = 0.f; s_c[2] = -1e30f; }

#pragma unroll
    for (int i = 0; i < 8; i++) {
        const int j = i * 256 + tid;
        cp16(sxb + (uint32_t)j * 16u, xbase + (size_t)j * 16);
    }
    cp_commit();

    float acc0 = 0.f, acc1 = 0.f;
    const int e0 = tid, e1 = tid + 256;

    for (int tile = 0; tile < T_ / TC_; tile++) {
        const int buf = tile & 1;
        if (tile + 1 < T_ / TC_) {
            const uint32_t db = sxb + (uint32_t)((tile + 1) & 1) * (TC_ * E_ * 4);
            const char* src = xbase + (size_t)(tile + 1) * TC_ * E_ * 4;
#pragma unroll
            for (int i = 0; i < 8; i++) {
                const int j = i * 256 + tid;
                cp16(db + (uint32_t)j * 16u, src + (size_t)j * 16);
            }
            cp_commit();
            cp_wait<1>();
        } else {
            cp_wait<0>();
        }
        __syncthreads();

        const float* xt = s_x + buf * (TC_ * E_);
#pragma unroll
        for (int rr = 0; rr < 2; rr++) {
            const int r = wid + rr * 8;
            const float* row = xt + r * E_;
            float s = 0.f;
#pragma unroll 4
            for (int e = lane; e < E_; e += 32) s += row[e] * s_v[e];
#pragma unroll
            for (int o = 16; o; o >>= 1) s += __shfl_xor_sync(0xffffffffu, s, o);
            if (lane == 0) s_p[r] = s;
        }
        __syncthreads();

        if (wid == 0) {
            float sc = (lane < TC_) ? s_p[lane] : -1e30f;
            float tm = sc;
#pragma unroll
            for (int o = 16; o; o >>= 1) tm = fmaxf(tm, __shfl_xor_sync(0xffffffffu, tm, o));
            const float m_old = s_c[2];
            const float m_new = fmaxf(m_old, tm);
            const float fac = expf(m_old - m_new);
            float p = (lane < TC_) ? expf(sc - m_new) : 0.f;
            float ps = p;
#pragma unroll
            for (int o = 16; o; o >>= 1) ps += __shfl_xor_sync(0xffffffffu, ps, o);
            if (lane < TC_) s_p[lane] = p;
            if (lane == 0) {
                s_c[0] = fac;
                s_c[1] = s_c[1] * fac + ps;
                s_c[2] = m_new;
            }
        }
        __syncthreads();

        const float fac = s_c[0];
        acc0 *= fac;
        acc1 *= fac;
#pragma unroll
        for (int r = 0; r < TC_; r++) {
            const float p = s_p[r];
            acc0 += p * xt[r * E_ + e0];
            acc1 += p * xt[r * E_ + e1];
        }
        __syncthreads();
    }

    const float inv = 1.0f / s_c[1];
    float* dst = xbar + ((size_t)b * L_ + l) * E_;
    dst[e0] = acc0 * inv;
    dst[e1] = acc1 * inv;
}

// ---------------- pooled = xbar @ We2 + be2 ----------------
__global__ void __launch_bounds__(128)
pooledg_kernel(const float* __restrict__ xbar, const float* __restrict__ We2,
               const float* __restrict__ be2, float* __restrict__ pooled, int l_base)
{
    const int l = l_base + blockIdx.y;
    const int f = blockIdx.x * 128 + threadIdx.x;
    const int tid = threadIdx.x;

    __shared__ float s_x[B_ * E_];
    for (int i = tid; i < B_ * E_; i += 128) {
        const int b = i >> 9, e = i & 511;
        s_x[i] = xbar[((size_t)b * L_ + l) * E_ + e];
    }
    __syncthreads();

    float acc[B_];
#pragma unroll
    for (int b = 0; b < B_; b++) acc[b] = 0.f;

    const float* wcol = We2 + (size_t)l * E_ * E_ + f;
#pragma unroll 4
    for (int e = 0; e < E_; e++) {
        const float w = wcol[(size_t)e * E_];
#pragma unroll
        for (int b = 0; b < B_; b++) acc[b] += s_x[b * E_ + e] * w;
    }
    const float bias = be2[l * E_ + f];
#pragma unroll
    for (int b = 0; b < B_; b++)
        pooled[((size_t)b * L_ + l) * E_ + f] = acc[b] + bias;
}

// ---------------- router GEMM: partial sums over 16 k-slices ----------------
__global__ void __launch_bounds__(256)
router_gemm_kernel(const float* __restrict__ pooled,
                   const float* __restrict__ Wr1, const float* __restrict__ Wn,
                   float* __restrict__ part)
{
    const int s = blockIdx.x, b = blockIdx.y;
    const int tid = threadIdx.x;
    const float* ri = pooled + (size_t)b * RIN_ + s * 768;

    float acc = 0.f;
    if (tid < 128) {
        const float* w = Wr1 + (size_t)s * 768 * 128 + tid;
#pragma unroll 8
        for (int k = 0; k < 768; k++) acc += ri[k] * w[(size_t)k * 128];
        part[(s * 16 + b) * 152 + tid] = acc;
    } else if (tid < 152) {
        const float* w = Wn + (size_t)s * 768 * 24 + (tid - 128);
#pragma unroll 8
        for (int k = 0; k < 768; k++) acc += ri[k] * w[(size_t)k * 24];
        part[(s * 16 + b) * 152 + tid] = acc;
    }
}

// ---------------- router tail ----------------
__global__ void __launch_bounds__(256)
router_tail_kernel(const float* __restrict__ pooled, const float* __restrict__ noise,
                   const float* __restrict__ part,
                   const float* __restrict__ br1,
                   const float* __restrict__ Wr2, const float* __restrict__ br2,
                   const float* __restrict__ bn,
                   const float* __restrict__ ln_g, const float* __restrict__ ln_b,
                   const float* __restrict__ Wc1, const float* __restrict__ bc1,
                   const float* __restrict__ Wc2, const float* __restrict__ bc2,
                   float* __restrict__ out_logits, float* __restrict__ out_rw,
                   float* __restrict__ out_fn)
{
    const int b = blockIdx.x;
    const int tid = threadIdx.x;
    const int lane = tid & 31, wid = tid >> 5;
    const float* ri = pooled + (size_t)b * RIN_;

    __shared__ float s_rh[128];
    __shared__ float s_nlin[L_];
    __shared__ float s_rw[L_];
    __shared__ float s_f[E_];
    __shared__ float s_hc[256];
    __shared__ float s_red[32];

    if (tid < 152) {
        float acc = 0.f;
#pragma unroll
        for (int s = 0; s < 16; s++) acc += part[(s * 16 + b) * 152 + tid];
        if (tid < 128) s_rh[tid] = fmaxf(acc + br1[tid], 0.f);
        else           s_nlin[tid - 128] = acc + bn[tid - 128];
    }
    __syncthreads();

    if (tid < L_) {
        float acc = 0.f;
#pragma unroll
        for (int k = 0; k < 128; k++) acc += s_rh[k] * Wr2[k * L_ + tid];
        const float lg = acc + br2[tid];
        const float x = s_nlin[tid];
        const float ns = (x > 20.f) ? x : log1pf(expf(x));
        const float z = (lg + noise[b * L_ + tid] * ns) / TEMP_;
        const float sig = 1.f / (1.f + expf(-z));
        const float rw = ALPHA_ * sig + UNIF_;
        s_rw[tid] = rw;
        out_rw[b * L_ + tid] = rw;
    }
    __syncthreads();

    float fv[2];
#pragma unroll
    for (int rr = 0; rr < 2; rr++) {
        const int e = tid + rr * 256;
        float acc = 0.f;
#pragma unroll
        for (int ll = 0; ll < L_; ll++) acc += ri[ll * E_ + e] * s_rw[ll];
        s_f[e] = acc;
        fv[rr] = acc;
    }
    float lsum = fv[0] + fv[1];
    float lsq  = fv[0] * fv[0] + fv[1] * fv[1];
#pragma unroll
    for (int o = 16; o; o >>= 1) {
        lsum += __shfl_xor_sync(0xffffffffu, lsum, o);
        lsq  += __shfl_xor_sync(0xffffffffu, lsq,  o);
    }
    if (lane == 0) { s_red[wid] = lsum; s_red[wid + 8] = lsq; }
    __syncthreads();
    if (tid == 0) {
        float su = 0.f, sq = 0.f;
        for (int w = 0; w < 8; w++) { su += s_red[w]; sq += s_red[w + 8]; }
        const float mu = su / (float)E_;
        const float var = sq / (float)E_ - mu * mu;
        s_red[0] = mu;
        s_red[1] = rsqrtf(var + 1e-5f);
    }
    __syncthreads();
    const float mu = s_red[0], rstd = s_red[1];
#pragma unroll
    for (int rr = 0; rr < 2; rr++) {
        const int e = tid + rr * 256;
        const float fn = (s_f[e] - mu) * rstd * ln_g[e] + ln_b[e];
        s_f[e] = fn;
        out_fn[(size_t)b * E_ + e] = fn;
    }
    __syncthreads();

    {
        const float* w = Wc1 + tid;
        float acc = 0.f;
#pragma unroll 8
        for (int e = 0; e < E_; e++) { acc += s_f[e] * (*w); w += 256; }
        s_hc[tid] = fmaxf(acc + bc1[tid], 0.f);
    }
    __syncthreads();

    if (tid < 2) {
        float acc = 0.f;
#pragma unroll 8
        for (int j = 0; j < 256; j++) acc += s_hc[j] * Wc2[j * 2 + tid];
        out_logits[b * 2 + tid] = acc + bc2[tid];
    }
}

// ---------------- launch: three-segment fork/join pipeline ----------
extern "C" void kernel_launch(void* const* d_in, const int* in_sizes, int n_in,
                              void* d_out, int out_size)
{
    const float* h    = (const float*)d_in[0];
    const float* noise= (const float*)d_in[1];
    const float* We1  = (const float*)d_in[2];
    const float* be1  = (const float*)d_in[3];
    const float* We2  = (const float*)d_in[4];
    const float* be2  = (const float*)d_in[5];
    const float* wa   = (const float*)d_in[6];
    const float* Wr1  = (const float*)d_in[8];
    const float* br1  = (const float*)d_in[9];
    const float* Wr2  = (const float*)d_in[10];
    const float* br2  = (const float*)d_in[11];
    const float* Wn   = (const float*)d_in[12];
    const float* bn   = (const float*)d_in[13];
    const float* ln_g = (const float*)d_in[14];
    const float* ln_b = (const float*)d_in[15];
    const float* Wc1  = (const float*)d_in[16];
    const float* bc1  = (const float*)d_in[17];
    const float* Wc2  = (const float*)d_in[18];
    const float* bc2  = (const float*)d_in[19];

    __half *Ah, *B1;
    float *x1, *v, *xbar, *rpart;
    cudaGetSymbolAddress((void**)&Ah,  g_Ah);
    cudaGetSymbolAddress((void**)&B1,  g_B1);
    cudaGetSymbolAddress((void**)&x1,  g_x1);
    cudaGetSymbolAddress((void**)&v,   g_v);
    cudaGetSymbolAddress((void**)&xbar, g_xbar);
    cudaGetSymbolAddress((void**)&rpart, g_rpart);

    float* out = (float*)d_out;
    float* out_logits = out + OUT_LOGITS;
    float* out_rw     = out + OUT_RW;
    float* out_fn     = out + OUT_FN;
    float* out_pooled = out + OUT_POOLED;

    cudaFuncSetAttribute(mma_gemm_kernel,
                         cudaFuncAttributeMaxDynamicSharedMemorySize, SMEM_TOT);
    cudaFuncSetAttribute(pool2_kernel,
                         cudaFuncAttributeMaxDynamicSharedMemorySize, P2_SMEM);

    cudaStream_t sp;
    cudaStreamCreateWithFlags(&sp, cudaStreamNonBlocking);
    cudaEvent_t e1, e2a, e2, e3, e5;
    cudaEventCreateWithFlags(&e1,  cudaEventDisableTiming);
    cudaEventCreateWithFlags(&e2a, cudaEventDisableTiming);
    cudaEventCreateWithFlags(&e2,  cudaEventDisableTiming);
    cudaEventCreateWithFlags(&e3,  cudaEventDisableTiming);
    cudaEventCreateWithFlags(&e5,  cudaEventDisableTiming);

    // main: conv segment [0,6)  (only ~38us of exposed serial prologue)
    conv_h_kernel<<<dim3(3200, 1, LQ_), 256>>>(h, Ah, 0);
    conv_w_kernel<<<dim3(16, 8, LQ_), 256>>>(We1, B1, 0);
    cudaEventRecord(e1, 0);

    // side: conv [6,12), then conv [12,24) + vwa
    cudaStreamWaitEvent(sp, e1, 0);
    conv_h_kernel<<<dim3(3200, 1, LQ_), 256, 0, sp>>>(h, Ah, LQ_);
    conv_w_kernel<<<dim3(16, 8, LQ_), 256, 0, sp>>>(We1, B1, LQ_);
    cudaEventRecord(e2a, sp);
    conv_h_kernel<<<dim3(3200, 1, LH_), 256, 0, sp>>>(h, Ah, LH_);
    conv_w_kernel<<<dim3(16, 8, LH_), 256, 0, sp>>>(We1, B1, LH_);
    vwa_kernel<<<dim3(4, L_), 256, 0, sp>>>(We2, wa, v);
    cudaEventRecord(e2, sp);

    // main: gemm [0,6); gemm [6,12); gemm [12,24)
    mma_gemm_kernel<<<dim3(4, 50, LQ_), 256, SMEM_TOT>>>(Ah, B1, be1, x1, 0);
    cudaStreamWaitEvent(0, e2a, 0);
    mma_gemm_kernel<<<dim3(4, 50, LQ_), 256, SMEM_TOT>>>(Ah, B1, be1, x1, LQ_);
    cudaEventRecord(e3, 0);   // x1[0,12) done
    cudaStreamWaitEvent(0, e2, 0);
    mma_gemm_kernel<<<dim3(4, 50, LH_), 256, SMEM_TOT>>>(Ah, B1, be1, x1, LH_);

    // side: pool half1 (l 0..12) overlaps gemm [12,24)
    cudaStreamWaitEvent(sp, e3, 0);
    pool2_kernel<<<B_ * LH_, 256, P2_SMEM, sp>>>(x1, v, xbar, 0);
    pooledg_kernel<<<dim3(4, LH_), 128, 0, sp>>>(xbar, We2, be2, out_pooled, 0);
    cudaEventRecord(e5, sp);

    // main: pool half2, join, router
    pool2_kernel<<<B_ * LH_, 256, P2_SMEM>>>(x1, v, xbar, LH_);
    pooledg_kernel<<<dim3(4, LH_), 128>>>(xbar, We2, be2, out_pooled, LH_);
    cudaStreamWaitEvent(0, e5, 0);
    router_gemm_kernel<<<dim3(16, 16), 256>>>(out_pooled, Wr1, Wn, rpart);
    router_tail_kernel<<<B_, 256>>>(out_pooled, noise, rpart, br1, Wr2, br2, bn,
                                    ln_g, ln_b, Wc1, bc1, Wc2, bc2,
                                    out_logits, out_rw, out_fn);
}

// round 16
// speedup vs baseline: 1.0263x; 1.0009x over previous
#include <cuda_runtime.h>
#include <cuda_fp16.h>
#include <cstdint>

// ---------------- constants ----------------
#define B_   16
#define L_   24
#define LH_  12
#define LS1_ 4
#define LS2_ 8
#define T_   400
#define D_   1024
#define E_   512
#define M_   6400
#define RIN_ 12288
#define TEMP_ 1.75f
#define ALPHA_ 0.325f
#define UNIF_ (0.675f / 24.0f)

#define OUT_LOGITS 0
#define OUT_RW     32
#define OUT_FN     416
#define OUT_POOLED 8608

// ---------------- scratch (device globals; no allocation) ----------------
__device__ __half g_Ah [(size_t)L_ * M_ * D_];   // h fp16  [l][m][k]
__device__ __half g_B1 [(size_t)L_ * E_ * D_];   // We1^T fp16 [l][n][k]
__device__ float g_x1[(size_t)L_ * M_ * E_];     // relu(h@We1+be1) fp32
__device__ float g_v [(size_t)L_ * E_];          // We2 . wa  per l
__device__ float g_xbar[(size_t)B_ * L_ * E_];   // softmax-weighted x1
__device__ float g_rpart[16 * 16 * 152];         // router partials

// ---------------- PTX helpers ----------------
__device__ __forceinline__ uint32_t smem_u32(const void* p) {
    uint32_t a;
    asm("{ .reg .u64 t; cvta.to.shared.u64 t, %1; cvt.u32.u64 %0, t; }" : "=r"(a) : "l"(p));
    return a;
}
__device__ __forceinline__ void cp16(uint32_t dst, const void* src) {
    asm volatile("cp.async.cg.shared.global [%0], [%1], 16;" :: "r"(dst), "l"(src));
}
__device__ __forceinline__ void cp_commit() {
    asm volatile("cp.async.commit_group;" ::: "memory");
}
template<int N>
__device__ __forceinline__ void cp_wait() {
    asm volatile("cp.async.wait_group %0;" :: "n"(N) : "memory");
}
__device__ __forceinline__ void ldsm4(uint32_t r[4], uint32_t addr) {
    asm volatile("ldmatrix.sync.aligned.m8n8.x4.shared.b16 {%0,%1,%2,%3}, [%4];"
                 : "=r"(r[0]), "=r"(r[1]), "=r"(r[2]), "=r"(r[3]) : "r"(addr));
}
__device__ __forceinline__ void mma_fp16(float d[4], const uint32_t a[4],
                                         uint32_t b0, uint32_t b1) {
    asm volatile(
        "mma.sync.aligned.m16n8k16.row.col.f32.f16.f16.f32 "
        "{%0,%1,%2,%3}, {%4,%5,%6,%7}, {%8,%9}, {%0,%1,%2,%3};"
        : "+f"(d[0]), "+f"(d[1]), "+f"(d[2]), "+f"(d[3])
        : "r"(a[0]), "r"(a[1]), "r"(a[2]), "r"(a[3]), "r"(b0), "r"(b1));
}

union H8 { __half b[8]; uint4 u; };

// ---------------- conversion: h -> row-major fp16 ----------------
__global__ void __launch_bounds__(256)
conv_h_kernel(const float* __restrict__ h, __half* __restrict__ Ah, int l_base)
{
    const int l  = l_base + blockIdx.z;
    const int gi = blockIdx.x * 256 + threadIdx.x;
    const int m  = gi >> 7;
    const int k0 = (gi & 127) * 8;
    const int b  = m / 400, t = m - b * 400;

    const float* src = h + (((size_t)(b * L_ + l) * T_ + t) * (size_t)D_ + k0);
    float4 v0 = *(const float4*)src;
    float4 v1 = *(const float4*)(src + 4);
    float v[8] = {v0.x, v0.y, v0.z, v0.w, v1.x, v1.y, v1.z, v1.w};

    H8 hv;
#pragma unroll
    for (int i = 0; i < 8; i++) hv.b[i] = __float2half(v[i]);
    *(uint4*)(Ah + ((size_t)l * M_ + m) * (size_t)D_ + k0) = hv.u;
}

// ---------------- conv_w: We1[l][K][512] -> [l][n][K] fp16 (transposed) ----------
__global__ void __launch_bounds__(256)
conv_w_kernel(const float* __restrict__ W, __half* __restrict__ Bo, int l_base)
{
    const int K = D_;
    const int l  = l_base + blockIdx.z;
    const int n0 = blockIdx.y * 64;
    const int k0 = blockIdx.x * 64;
    const int tid = threadIdx.x;

    __shared__ float s_w[64 * 65];

#pragma unroll
    for (int it = 0; it < 4; it++) {
        const int idx = it * 256 + tid;
        const int kr = idx >> 4;
        const int c4 = idx & 15;
        float4 v = *(const float4*)(W + ((size_t)l * K + k0 + kr) * 512 + n0 + c4 * 4);
        float* d = s_w + kr * 65 + c4 * 4;
        d[0] = v.x; d[1] = v.y; d[2] = v.z; d[3] = v.w;
    }
    __syncthreads();

#pragma unroll
    for (int it = 0; it < 2; it++) {
        const int idx = it * 256 + tid;
        const int nl  = idx >> 3;
        const int kc8 = idx & 7;
        H8 hv;
#pragma unroll
        for (int j = 0; j < 8; j++)
            hv.b[j] = __float2half(s_w[(kc8 * 8 + j) * 65 + nl]);
        const size_t o = ((size_t)l * 512 + n0 + nl) * (size_t)K + k0 + kc8 * 8;
        *(uint4*)(Bo + o) = hv.u;
    }
}

// ---------------- v = We2 . wa ----------------
__global__ void __launch_bounds__(256)
vwa_kernel(const float* __restrict__ We2, const float* __restrict__ wa,
           float* __restrict__ v)
{
    const int l = blockIdx.y;
    const int e0 = blockIdx.x * 128;
    const int tid = threadIdx.x;
    const int lane = tid & 31, wid = tid >> 5;
    __shared__ float s_wa[E_];
    for (int f = tid; f < E_; f += 256) s_wa[f] = wa[f];
    __syncthreads();
    for (int e = e0 + wid; e < e0 + 128; e += 8) {
        const float* row = We2 + ((size_t)l * E_ + e) * E_;
        float s = 0.f;
        for (int f = lane; f < E_; f += 32) s += row[f] * s_wa[f];
#pragma unroll
        for (int o = 16; o; o >>= 1) s += __shfl_xor_sync(0xffffffffu, s, o);
        if (lane == 0) v[l * E_ + e] = s;
    }
}

// ---------------- fp16 single-term GEMM, fragment double-buffered ----------------
#define STAGE_ 32768
#define SMEM_TOT (3 * STAGE_)

__global__ void __launch_bounds__(256, 2)
mma_gemm_kernel(const __half* __restrict__ Ag, const __half* __restrict__ Bw,
                const float* __restrict__ bias, float* __restrict__ Cf, int l_base)
{
    constexpr int K = D_;
    constexpr int NK = K / 64;
    extern __shared__ __align__(128) char smem[];
    const uint32_t sb = smem_u32(smem);
    const int tid = threadIdx.x;
    const int lane = tid & 31, wid = tid >> 5;
    const int nt = blockIdx.x, bm = blockIdx.y;
    const int l = l_base + blockIdx.z;

    const char* srcs[8];
    uint32_t dsto[8];
#pragma unroll
    for (int t = 0; t < 8; t++) {
        const int j = tid + t * 256;
        const bool isA = j < 1024;
        const int idx = j & 1023;
        const int row = idx >> 3;
        const int c   = idx & 7;
        size_t base;
        const __half* gb;
        if (isA) {
            gb = Ag;
            base = ((size_t)l * M_ + (size_t)bm * 128 + row) * (size_t)K + c * 8;
        } else {
            gb = Bw;
            base = ((size_t)l * 512 + (size_t)nt * 128 + row) * (size_t)K + c * 8;
        }
        srcs[t] = (const char*)(gb + base);
        dsto[t] = (isA ? 0u : 16384u) + (uint32_t)row * 128u +
                  (uint32_t)((c ^ (row & 7)) * 16);
    }

#define ISSUE_STAGE(S)                                              \
    do {                                                            \
        const uint32_t stb_ = sb + (uint32_t)(S) * STAGE_;          \
        _Pragma("unroll")                                           \
        for (int t = 0; t < 8; t++) cp16(stb_ + dsto[t], srcs[t]);  \
        _Pragma("unroll")                                           \
        for (int t = 0; t < 8; t++) srcs[t] += 128;                 \
        cp_commit();                                                \
    } while (0)

    ISSUE_STAGE(0);
    ISSUE_STAGE(1);

    float acc[4][4][4];
#pragma unroll
    for (int i = 0; i < 4; i++)
#pragma unroll
        for (int j = 0; j < 4; j++)
#pragma unroll
            for (int r = 0; r < 4; r++) acc[i][j][r] = 0.f;

    const int wm = (wid & 1) * 64;
    const int wn = (wid >> 1) * 32;
    const int lr = lane & 15;
    const int lc = lane >> 4;

#define LOADFRAG(AF, BF, KS)                                               \
    do {                                                                   \
        const int ch_ = (KS) * 2 + lc;                                     \
        _Pragma("unroll")                                                  \
        for (int i = 0; i < 4; i++) {                                      \
            const int row_ = wm + i * 16 + lr;                             \
            ldsm4(AF[i], sA + (uint32_t)row_ * 128u +                      \
                          (uint32_t)(((ch_) ^ (row_ & 7)) * 16));          \
        }                                                                  \
        _Pragma("unroll")                                                  \
        for (int j = 0; j < 2; j++) {                                      \
            const int row_ = wn + j * 16 + lr;                             \
            ldsm4(BF[j], sB + (uint32_t)row_ * 128u +                      \
                          (uint32_t)(((ch_) ^ (row_ & 7)) * 16));          \
        }                                                                  \
    } while (0)

#define MMASET(AF, BF)                                                     \
    do {                                                                   \
        _Pragma("unroll")                                                  \
        for (int i = 0; i < 4; i++)                                        \
            _Pragma("unroll")                                              \
            for (int j = 0; j < 2; j++)                                    \
                _Pragma("unroll")                                          \
                for (int hf = 0; hf < 2; hf++)                             \
                    mma_fp16(acc[i][j * 2 + hf], AF[i], BF[j][hf], BF[j][hf + 2]); \
    } while (0)

    for (int kc = 0; kc < NK; kc++) {
        cp_wait<1>();
        __syncthreads();
        const int s = kc % 3;
        if (kc + 2 < NK) { ISSUE_STAGE((kc + 2) % 3); }
        else             { cp_commit(); }

        const uint32_t sA = sb + (uint32_t)s * STAGE_;
        const uint32_t sB = sA + 16384u;

        uint32_t a0[4][4], b0[2][4], a1[4][4], b1[2][4];
        LOADFRAG(a0, b0, 0);
        LOADFRAG(a1, b1, 1);
        MMASET(a0, b0);
        LOADFRAG(a0, b0, 2);
        MMASET(a1, b1);
        LOADFRAG(a1, b1, 3);
        MMASET(a0, b0);
        MMASET(a1, b1);
    }
#undef ISSUE_STAGE
#undef LOADFRAG
#undef MMASET

    const int lq = lane >> 2;
    const int lp = (lane & 3) * 2;
#pragma unroll
    for (int j2 = 0; j2 < 4; j2++) {
        const int n_g = nt * 128 + wn + j2 * 8 + lp;
        const float b0v = bias[l * 512 + n_g];
        const float b1v = bias[l * 512 + n_g + 1];
#pragma unroll
        for (int i = 0; i < 4; i++) {
#pragma unroll
            for (int rh = 0; rh < 2; rh++) {
                const int m_g = bm * 128 + wm + i * 16 + lq + rh * 8;
                float v0 = fmaxf(acc[i][j2][rh * 2 + 0] + b0v, 0.f);
                float v1 = fmaxf(acc[i][j2][rh * 2 + 1] + b1v, 0.f);
                const size_t o = ((size_t)l * M_ + m_g) * 512 + n_g;
                *(float2*)(Cf + o) = make_float2(v0, v1);
            }
        }
    }
}

// ---------------- pool2: single-pass online softmax + weighted sum ----------------
#define TC_ 16
#define P2_XBUF (2 * TC_ * E_ * 4)
#define P2_SMEM (P2_XBUF + E_ * 4 + 256)

__global__ void __launch_bounds__(256)
pool2_kernel(const float* __restrict__ x1, const float* __restrict__ v,
             float* __restrict__ xbar, int l_base)
{
    extern __shared__ __align__(16) char psm[];
    float* s_x  = (float*)psm;
    float* s_v  = (float*)(psm + P2_XBUF);
    float* s_p  = (float*)(psm + P2_XBUF + E_ * 4);
    float* s_c  = s_p + TC_;
    const uint32_t sxb = smem_u32(s_x);

    const int b = blockIdx.x / LH_;
    const int l = l_base + blockIdx.x % LH_;
    const char* xbase = (const char*)(x1 + ((size_t)l * M_ + (size_t)b * T_) * E_);

    const int tid = threadIdx.x;
    const int lane = tid & 31, wid = tid >> 5;

    for (int e = tid; e < E_; e += 256) s_v[e] = v[l * E_ + e];
    if (tid == 0) { s_c[1] = 0.f; s_c[2] = -1e30f; }

#pragma unroll
    for (int i = 0; i < 8; i++) {
        const int j = i * 256 + tid;
        cp16(sxb + (uint32_t)j * 16u, xbase + (size_t)j * 16);
    }
    cp_commit();

    float acc0 = 0.f, acc1 = 0.f;
    const int e0 = tid, e1 = tid + 256;

    for (int tile = 0; tile < T_ / TC_; tile++) {
        const int buf = tile & 1;
        if (tile + 1 < T_ / TC_) {
            const uint32_t db = sxb + (uint32_t)((tile + 1) & 1) * (TC_ * E_ * 4);
            const char* src = xbase + (size_t)(tile + 1) * TC_ * E_ * 4;
#pragma unroll
            for (int i = 0; i < 8; i++) {
                const int j = i * 256 + tid;
                cp16(db + (uint32_t)j * 16u, src + (size_t)j * 16);
            }
            cp_commit();
            cp_wait<1>();
        } else {
            cp_wait<0>();
        }
        __syncthreads();

        const float* xt = s_x + buf * (TC_ * E_);
#pragma unroll
        for (int rr = 0; rr < 2; rr++) {
            const int r = wid + rr * 8;
            const float* row = xt + r * E_;
            float s = 0.f;
#pragma unroll 4
            for (int e = lane; e < E_; e += 32) s += row[e] * s_v[e];
#pragma unroll
            for (int o = 16; o; o >>= 1) s += __shfl_xor_sync(0xffffffffu, s, o);
            if (lane == 0) s_p[r] = s;
        }
        __syncthreads();

        if (wid == 0) {
            float sc = (lane < TC_) ? s_p[lane] : -1e30f;
            float tm = sc;
#pragma unroll
            for (int o = 16; o; o >>= 1) tm = fmaxf(tm, __shfl_xor_sync(0xffffffffu, tm, o));
            const float m_old = s_c[2];
            const float m_new = fmaxf(m_old, tm);
            const float fac = expf(m_old - m_new);
            float p = (lane < TC_) ? expf(sc - m_new) : 0.f;
            float ps = p;
#pragma unroll
            for (int o = 16; o; o >>= 1) ps += __shfl_xor_sync(0xffffffffu, ps, o);
            if (lane < TC_) s_p[lane] = p;
            if (lane == 0) {
                s_c[0] = fac;
                s_c[1] = s_c[1] * fac + ps;
                s_c[2] = m_new;
            }
        }
        __syncthreads();

        const float fac = s_c[0];
        acc0 *= fac;
        acc1 *= fac;
#pragma unroll
        for (int r = 0; r < TC_; r++) {
            const float p = s_p[r];
            acc0 += p * xt[r * E_ + e0];
            acc1 += p * xt[r * E_ + e1];
        }
        __syncthreads();
    }

    const float inv = 1.0f / s_c[1];
    float* dst = xbar + ((size_t)b * L_ + l) * E_;
    dst[e0] = acc0 * inv;
    dst[e1] = acc1 * inv;
}

// ---------------- pooled = xbar @ We2 + be2 ----------------
__global__ void __launch_bounds__(128)
pooledg_kernel(const float* __restrict__ xbar, const float* __restrict__ We2,
               const float* __restrict__ be2, float* __restrict__ pooled, int l_base)
{
    const int l = l_base + blockIdx.y;
    const int f = blockIdx.x * 128 + threadIdx.x;
    const int tid = threadIdx.x;

    __shared__ float s_x[B_ * E_];
    for (int i = tid; i < B_ * E_; i += 128) {
        const int b = i >> 9, e = i & 511;
        s_x[i] = xbar[((size_t)b * L_ + l) * E_ + e];
    }
    __syncthreads();

    float acc[B_];
#pragma unroll
    for (int b = 0; b < B_; b++) acc[b] = 0.f;

    const float* wcol = We2 + (size_t)l * E_ * E_ + f;
#pragma unroll 4
    for (int e = 0; e < E_; e++) {
        const float w = wcol[(size_t)e * E_];
#pragma unroll
        for (int b = 0; b < B_; b++) acc[b] += s_x[b * E_ + e] * w;
    }
    const float bias = be2[l * E_ + f];
#pragma unroll
    for (int b = 0; b < B_; b++)
        pooled[((size_t)b * L_ + l) * E_ + f] = acc[b] + bias;
}

// ---------------- router GEMM: partial sums over 16 k-slices ----------------
__global__ void __launch_bounds__(256)
router_gemm_kernel(const float* __restrict__ pooled,
                   const float* __restrict__ Wr1, const float* __restrict__ Wn,
                   float* __restrict__ part)
{
    const int s = blockIdx.x, b = blockIdx.y;
    const int tid = threadIdx.x;
    const float* ri = pooled + (size_t)b * RIN_ + s * 768;

    float acc = 0.f;
    if (tid < 128) {
        const float* w = Wr1 + (size_t)s * 768 * 128 + tid;
#pragma unroll 8
        for (int k = 0; k < 768; k++) acc += ri[k] * w[(size_t)k * 128];
        part[(s * 16 + b) * 152 + tid] = acc;
    } else if (tid < 152) {
        const float* w = Wn + (size_t)s * 768 * 24 + (tid - 128);
#pragma unroll 8
        for (int k = 0; k < 768; k++) acc += ri[k] * w[(size_t)k * 24];
        part[(s * 16 + b) * 152 + tid] = acc;
    }
}

// ---------------- router tail ----------------
__global__ void __launch_bounds__(256)
router_tail_kernel(const float* __restrict__ pooled, const float* __restrict__ noise,
                   const float* __restrict__ part,
                   const float* __restrict__ br1,
                   const float* __restrict__ Wr2, const float* __restrict__ br2,
                   const float* __restrict__ bn,
                   const float* __restrict__ ln_g, const float* __restrict__ ln_b,
                   const float* __restrict__ Wc1, const float* __restrict__ bc1,
                   const float* __restrict__ Wc2, const float* __restrict__ bc2,
                   float* __restrict__ out_logits, float* __restrict__ out_rw,
                   float* __restrict__ out_fn)
{
    const int b = blockIdx.x;
    const int tid = threadIdx.x;
    const int lane = tid & 31, wid = tid >> 5;
    const float* ri = pooled + (size_t)b * RIN_;

    __shared__ float s_rh[128];
    __shared__ float s_nlin[L_];
    __shared__ float s_rw[L_];
    __shared__ float s_f[E_];
    __shared__ float s_hc[256];
    __shared__ float s_red[32];

    if (tid < 152) {
        float acc = 0.f;
#pragma unroll
        for (int s = 0; s < 16; s++) acc += part[(s * 16 + b) * 152 + tid];
        if (tid < 128) s_rh[tid] = fmaxf(acc + br1[tid], 0.f);
        else           s_nlin[tid - 128] = acc + bn[tid - 128];
    }
    __syncthreads();

    if (tid < L_) {
        float acc = 0.f;
#pragma unroll
        for (int k = 0; k < 128; k++) acc += s_rh[k] * Wr2[k * L_ + tid];
        const float lg = acc + br2[tid];
        const float x = s_nlin[tid];
        const float ns = (x > 20.f) ? x : log1pf(expf(x));
        const float z = (lg + noise[b * L_ + tid] * ns) / TEMP_;
        const float sig = 1.f / (1.f + expf(-z));
        const float rw = ALPHA_ * sig + UNIF_;
        s_rw[tid] = rw;
        out_rw[b * L_ + tid] = rw;
    }
    __syncthreads();

    float fv[2];
#pragma unroll
    for (int rr = 0; rr < 2; rr++) {
        const int e = tid + rr * 256;
        float acc = 0.f;
#pragma unroll
        for (int ll = 0; ll < L_; ll++) acc += ri[ll * E_ + e] * s_rw[ll];
        s_f[e] = acc;
        fv[rr] = acc;
    }
    float lsum = fv[0] + fv[1];
    float lsq  = fv[0] * fv[0] + fv[1] * fv[1];
#pragma unroll
    for (int o = 16; o; o >>= 1) {
        lsum += __shfl_xor_sync(0xffffffffu, lsum, o);
        lsq  += __shfl_xor_sync(0xffffffffu, lsq,  o);
    }
    if (lane == 0) { s_red[wid] = lsum; s_red[wid + 8] = lsq; }
    __syncthreads();
    if (tid == 0) {
        float su = 0.f, sq = 0.f;
        for (int w = 0; w < 8; w++) { su += s_red[w]; sq += s_red[w + 8]; }
        const float mu = su / (float)E_;
        const float var = sq / (float)E_ - mu * mu;
        s_red[0] = mu;
        s_red[1] = rsqrtf(var + 1e-5f);
    }
    __syncthreads();
    const float mu = s_red[0], rstd = s_red[1];
#pragma unroll
    for (int rr = 0; rr < 2; rr++) {
        const int e = tid + rr * 256;
        const float fn = (s_f[e] - mu) * rstd * ln_g[e] + ln_b[e];
        s_f[e] = fn;
        out_fn[(size_t)b * E_ + e] = fn;
    }
    __syncthreads();

    {
        const float* w = Wc1 + tid;
        float acc = 0.f;
#pragma unroll 8
        for (int e = 0; e < E_; e++) { acc += s_f[e] * (*w); w += 256; }
        s_hc[tid] = fmaxf(acc + bc1[tid], 0.f);
    }
    __syncthreads();

    if (tid < 2) {
        float acc = 0.f;
#pragma unroll 8
        for (int j = 0; j < 256; j++) acc += s_hc[j] * Wc2[j * 2 + tid];
        out_logits[b * 2 + tid] = acc + bc2[tid];
    }
}

// ---------------- launch: finer fork/join pipeline ----------
extern "C" void kernel_launch(void* const* d_in, const int* in_sizes, int n_in,
                              void* d_out, int out_size)
{
    const float* h    = (const float*)d_in[0];
    const float* noise= (const float*)d_in[1];
    const float* We1  = (const float*)d_in[2];
    const float* be1  = (const float*)d_in[3];
    const float* We2  = (const float*)d_in[4];
    const float* be2  = (const float*)d_in[5];
    const float* wa   = (const float*)d_in[6];
    const float* Wr1  = (const float*)d_in[8];
    const float* br1  = (const float*)d_in[9];
    const float* Wr2  = (const float*)d_in[10];
    const float* br2  = (const float*)d_in[11];
    const float* Wn   = (const float*)d_in[12];
    const float* bn   = (const float*)d_in[13];
    const float* ln_g = (const float*)d_in[14];
    const float* ln_b = (const float*)d_in[15];
    const float* Wc1  = (const float*)d_in[16];
    const float* bc1  = (const float*)d_in[17];
    const float* Wc2  = (const float*)d_in[18];
    const float* bc2  = (const float*)d_in[19];

    __half *Ah, *B1;
    float *x1, *v, *xbar, *rpart;
    cudaGetSymbolAddress((void**)&Ah,  g_Ah);
    cudaGetSymbolAddress((void**)&B1,  g_B1);
    cudaGetSymbolAddress((void**)&x1,  g_x1);
    cudaGetSymbolAddress((void**)&v,   g_v);
    cudaGetSymbolAddress((void**)&xbar, g_xbar);
    cudaGetSymbolAddress((void**)&rpart, g_rpart);

    float* out = (float*)d_out;
    float* out_logits = out + OUT_LOGITS;
    float* out_rw     = out + OUT_RW;
    float* out_fn     = out + OUT_FN;
    float* out_pooled = out + OUT_POOLED;

    cudaFuncSetAttribute(mma_gemm_kernel,
                         cudaFuncAttributeMaxDynamicSharedMemorySize, SMEM_TOT);
    cudaFuncSetAttribute(pool2_kernel,
                         cudaFuncAttributeMaxDynamicSharedMemorySize, P2_SMEM);

    cudaStream_t sp;
    cudaStreamCreateWithFlags(&sp, cudaStreamNonBlocking);
    cudaEvent_t f1, f2, f3, g2, j1;
    cudaEventCreateWithFlags(&f1, cudaEventDisableTiming);
    cudaEventCreateWithFlags(&f2, cudaEventDisableTiming);
    cudaEventCreateWithFlags(&f3, cudaEventDisableTiming);
    cudaEventCreateWithFlags(&g2, cudaEventDisableTiming);
    cudaEventCreateWithFlags(&j1, cudaEventDisableTiming);

    // main: conv segment [0,4)  (~26us exposed prologue)
    conv_h_kernel<<<dim3(3200, 1, LS1_), 256>>>(h, Ah, 0);
    conv_w_kernel<<<dim3(16, 8, LS1_), 256>>>(We1, B1, 0);
    cudaEventRecord(f1, 0);

    // side: conv [4,12), then conv [12,24) + vwa
    cudaStreamWaitEvent(sp, f1, 0);
    conv_h_kernel<<<dim3(3200, 1, LS2_), 256, 0, sp>>>(h, Ah, LS1_);
    conv_w_kernel<<<dim3(16, 8, LS2_), 256, 0, sp>>>(We1, B1, LS1_);
    cudaEventRecord(f2, sp);
    conv_h_kernel<<<dim3(3200, 1, LH_), 256, 0, sp>>>(h, Ah, LH_);
    conv_w_kernel<<<dim3(16, 8, LH_), 256, 0, sp>>>(We1, B1, LH_);
    vwa_kernel<<<dim3(4, L_), 256, 0, sp>>>(We2, wa, v);
    cudaEventRecord(f3, sp);

    // main: gemm [0,4); [4,12); [12,24)
    mma_gemm_kernel<<<dim3(4, 50, LS1_), 256, SMEM_TOT>>>(Ah, B1, be1, x1, 0);
    cudaStreamWaitEvent(0, f2, 0);
    mma_gemm_kernel<<<dim3(4, 50, LS2_), 256, SMEM_TOT>>>(Ah, B1, be1, x1, LS1_);
    cudaEventRecord(g2, 0);   // x1[0,12) done
    cudaStreamWaitEvent(0, f3, 0);
    mma_gemm_kernel<<<dim3(4, 50, LH_), 256, SMEM_TOT>>>(Ah, B1, be1, x1, LH_);

    // side: pool [0,12) hidden under gemm [12,24)
    cudaStreamWaitEvent(sp, g2, 0);
    pool2_kernel<<<B_ * LH_, 256, P2_SMEM, sp>>>(x1, v, xbar, 0);
    pooledg_kernel<<<dim3(4, LH_), 128, 0, sp>>>(xbar, We2, be2, out_pooled, 0);
    cudaEventRecord(j1, sp);

    // main: pool [12,24), join, router
    pool2_kernel<<<B_ * LH_, 256, P2_SMEM>>>(x1, v, xbar, LH_);
    pooledg_kernel<<<dim3(4, LH_), 128>>>(xbar, We2, be2, out_pooled, LH_);
    cudaStreamWaitEvent(0, j1, 0);
    router_gemm_kernel<<<dim3(16, 16), 256>>>(out_pooled, Wr1, Wn, rpart);
    router_tail_kernel<<<B_, 256>>>(out_pooled, noise, rpart, br1, Wr2, br2, bn,
                                    ln_g, ln_b, Wc1, bc1, Wc2, bc2,
                                    out_logits, out_rw, out_fn);
}